// round 16
// baseline (speedup 1.0000x reference)
#include <cuda_runtime.h>
#include <cuda_bf16.h>
#include <cstdint>

#define BT_ 2048
#define V_  32000
#define HS_ 2048
#define HT_ 4096
#define S_CH 32
#define N_CH 96
#define T_CHN (N_CH - S_CH)
#define STAGE_B 32768
#define SMEM_BYTES (3*STAGE_B)
#define NTILES 4000
#define NCTA 296

__device__ float g_se[BT_], g_ss[BT_], g_tt[BT_], g_st[BT_], g_tv[BT_];
__device__ unsigned g_tile_ctr;
__device__ __align__(16) __nv_bfloat16 g_sb[(size_t)BT_*HS_];
__device__ __align__(16) __nv_bfloat16 g_wsb[(size_t)V_*HS_];
__device__ __align__(16) __nv_bfloat16 g_tb[(size_t)BT_*HT_];
__device__ __align__(16) __nv_bfloat16 g_wtb[(size_t)V_*HT_];
__device__ __align__(16) uint32_t g_stash[(size_t)BT_*V_/2];

#define M1 (BT_*HS_/8)
#define M2 (V_*HS_/8)
#define M3 (BT_*HT_/8)
#define M4 (V_*HT_/8)

__global__ void cvt_all_kernel(const float4* __restrict__ s0, const float4* __restrict__ s1,
                               const float4* __restrict__ s2, const float4* __restrict__ s3) {
    int i = blockIdx.x * blockDim.x + threadIdx.x;
    const float4* src; uint4* dst; int j;
    if (i < M1)                { src = s0; dst = (uint4*)g_sb;  j = i; }
    else if (i < M1+M2)        { src = s1; dst = (uint4*)g_wsb; j = i - M1; }
    else if (i < M1+M2+M3)     { src = s2; dst = (uint4*)g_tb;  j = i - (M1+M2); }
    else if (i < M1+M2+M3+M4)  { src = s3; dst = (uint4*)g_wtb; j = i - (M1+M2+M3); }
    else return;
    float4 a = src[2*j], b = src[2*j+1];
    __nv_bfloat162 p0 = __floats2bfloat162_rn(a.x, a.y);
    __nv_bfloat162 p1 = __floats2bfloat162_rn(a.z, a.w);
    __nv_bfloat162 p2 = __floats2bfloat162_rn(b.x, b.y);
    __nv_bfloat162 p3 = __floats2bfloat162_rn(b.z, b.w);
    uint4 o;
    o.x = *(uint32_t*)&p0; o.y = *(uint32_t*)&p1;
    o.z = *(uint32_t*)&p2; o.w = *(uint32_t*)&p3;
    dst[j] = o;
}
__global__ void zeroA_kernel() {
    int i = blockIdx.x * blockDim.x + threadIdx.x;
    if (i == 0) g_tile_ctr = 0u;
    if (i < 1024) { g_se[i]=0.f; g_ss[i]=0.f; g_tt[i]=0.f; g_st[i]=0.f; g_tv[i]=0.f; }
}
__global__ void zeroB_kernel() {
    int i = 1024 + blockIdx.x * blockDim.x + threadIdx.x;
    if (i < BT_) { g_se[i]=0.f; g_ss[i]=0.f; g_tt[i]=0.f; g_st[i]=0.f; g_tv[i]=0.f; }
}

__device__ __forceinline__ void cp16(uint32_t dst, const void* src) {
    asm volatile("cp.async.cg.shared.global [%0], [%1], 16;" :: "r"(dst), "l"(src) : "memory");
}
#define LDSM4(R0,R1,R2,R3,ADDR) \
    asm volatile("ldmatrix.sync.aligned.m8n8.x4.shared.b16 {%0,%1,%2,%3}, [%4];" \
        : "=r"(R0),"=r"(R1),"=r"(R2),"=r"(R3) : "r"(ADDR))
#define MMA(D,A0,A1,A2,A3,B0,B1) \
    asm volatile("mma.sync.aligned.m16n8k16.row.col.f32.bf16.bf16.f32 " \
        "{%0,%1,%2,%3},{%4,%5,%6,%7},{%8,%9},{%0,%1,%2,%3};" \
        : "+f"((D)[0]),"+f"((D)[1]),"+f"((D)[2]),"+f"((D)[3]) \
        : "r"(A0),"r"(A1),"r"(A2),"r"(A3),"r"(B0),"r"(B1))

#define ADV(s) s = ((s) == 2) ? 0 : (s) + 1
#define WAIT_SYNC() do { \
    asm volatile("cp.async.wait_group 1;" ::: "memory"); \
    __syncthreads(); } while (0)
#define COMMIT() asm volatile("cp.async.commit_group;" ::: "memory")

__global__ void __launch_bounds__(256, 2)
gemm_loss_kernel(const long long* __restrict__ target) {
    extern __shared__ char sm[];
    __shared__ unsigned sh_tile;
    const uint32_t sm0 = (uint32_t)__cvta_generic_to_shared(sm);
    const int tid = threadIdx.x, lane = tid & 31, wid = tid >> 5;
    const int wm = wid & 3, wn = wid >> 2;            // 4x2 warps, warp tile 32x64
    const int r8 = lane & 7, sel = lane >> 3;

    const int rowA = wm*32 + r8 + 8*(sel & 1);
    const uint32_t baseA = (uint32_t)(rowA * 128);
    const uint32_t xorA  = (uint32_t)(rowA & 7);
    const uint32_t uA    = (uint32_t)(sel >> 1);
    const int rowB = wn*64 + r8 + 8*(sel >> 1);
    const uint32_t baseB = 16384u + (uint32_t)(rowB * 128);
    const uint32_t xorB  = (uint32_t)(rowB & 7);
    const uint32_t uB    = (uint32_t)(sel & 1);

    const int prow = tid >> 3;
    const int pu   = tid & 7;
    const uint32_t pswz = (uint32_t)((pu ^ (prow & 7)) << 4);

    float acc[2][8][4];

    auto mma_block = [&](int s) {
        const uint32_t st = sm0 + (uint32_t)s * STAGE_B;
        #pragma unroll
        for (int ks = 0; ks < 4; ++ks) {
            uint32_t A0,A1,A2,A3, A4,A5,A6,A7;
            const uint32_t ua = 2u*ks + uA;
            LDSM4(A0,A1,A2,A3, st + baseA + ((ua ^ xorA) << 4));
            LDSM4(A4,A5,A6,A7, st + baseA + 2048 + ((ua ^ xorA) << 4));
            const uint32_t ub = 2u*ks + uB;
            #pragma unroll
            for (int jj = 0; jj < 4; ++jj) {
                uint32_t B0,B1,B2,B3;
                LDSM4(B0,B1,B2,B3, st + baseB + jj*2048 + ((ub ^ xorB) << 4));
                MMA(acc[0][2*jj],   A0,A1,A2,A3, B0,B1);
                MMA(acc[0][2*jj+1], A0,A1,A2,A3, B2,B3);
                MMA(acc[1][2*jj],   A4,A5,A6,A7, B0,B1);
                MMA(acc[1][2*jj+1], A4,A5,A6,A7, B2,B3);
            }
        }
    };

    for (;;) {
        __syncthreads();                              // smem stages + sh_tile safe to reuse
        if (tid == 0) sh_tile = atomicAdd(&g_tile_ctr, 1u);
        __syncthreads();
        const unsigned t = sh_tile;
        if (t >= NTILES) break;                       // uniform across CTA
        const int row0 = (int)(t & 15u) * 128;
        const int v0   = (int)(t >> 4) * 128;

        const __nv_bfloat16* aS = g_sb  + (size_t)row0*HS_ + (size_t)prow*HS_ + pu*8;
        const __nv_bfloat16* bS = g_wsb + (size_t)v0 *HS_ + (size_t)prow*HS_ + pu*8;
        const __nv_bfloat16* aT = g_tb  + (size_t)row0*HT_ + (size_t)prow*HT_ + pu*8;
        const __nv_bfloat16* bT = g_wtb + (size_t)v0 *HT_ + (size_t)prow*HT_ + pu*8;

        auto issue_body = [&](const __nv_bfloat16* asrc, const __nv_bfloat16* bsrc, int K, int s) {
            const uint32_t st = sm0 + (uint32_t)s * STAGE_B;
            #pragma unroll
            for (int i = 0; i < 4; ++i)
                cp16(st + (prow + i*32)*128 + pswz, asrc + (size_t)(i*32)*K);
            #pragma unroll
            for (int i = 0; i < 4; ++i)
                cp16(st + 16384 + (prow + i*32)*128 + pswz, bsrc + (size_t)(i*32)*K);
        };

        #pragma unroll
        for (int i = 0; i < 2; ++i)
            #pragma unroll
            for (int j = 0; j < 8; ++j)
                #pragma unroll
                for (int k = 0; k < 4; ++k) acc[i][j][k] = 0.f;

        int sIss = 2, sCon = 0;

        issue_body(aS,      bS,      HS_, 0); COMMIT();
        issue_body(aS + 64, bS + 64, HS_, 1); COMMIT();

        // student phase: consume 0..29, issue student c+2
        for (int c = 0; c < S_CH - 2; ++c) {
            WAIT_SYNC();
            issue_body(aS + (c + 2)*64, bS + (c + 2)*64, HS_, sIss); COMMIT(); ADV(sIss);
            mma_block(sCon); ADV(sCon);
        }
        // consume 30,31; issue teacher 0,1
        for (int c = 0; c < 2; ++c) {
            WAIT_SYNC();
            issue_body(aT + c*64, bT + c*64, HT_, sIss); COMMIT(); ADV(sIss);
            mma_block(sCon); ADV(sCon);
        }

        // ---- epilogue 1: student stats; stash s (bf16x2) to global
        #pragma unroll
        for (int im = 0; im < 2; ++im)
            #pragma unroll
            for (int h = 0; h < 2; ++h) {
                const int mloc = wm*32 + im*16 + (lane >> 2) + 8*h;
                const int row = row0 + mloc;
                const long long tg = target[row];
                const int tcol = (int)tg - v0;
                float se = 0.f, sq = 0.f, tval = 0.f; int hit = 0;
                #pragma unroll
                for (int jt = 0; jt < 8; ++jt) {
                    float x0 = acc[im][jt][2*h], x1 = acc[im][jt][2*h+1];
                    se += __expf(x0) + __expf(x1);
                    sq += x0*x0 + x1*x1;
                    const int nc = wn*64 + jt*8 + 2*(lane & 3);
                    if (nc == tcol)     { tval = x0; hit = 1; }
                    if (nc + 1 == tcol) { tval = x1; hit = 1; }
                    __nv_bfloat162 p = __floats2bfloat162_rn(x0, x1);
                    g_stash[((size_t)row * V_ + (v0 + nc)) >> 1] = *(uint32_t*)&p;
                }
                se += __shfl_xor_sync(~0u, se, 1); se += __shfl_xor_sync(~0u, se, 2);
                sq += __shfl_xor_sync(~0u, sq, 1); sq += __shfl_xor_sync(~0u, sq, 2);
                if ((lane & 3) == 0) { atomicAdd(g_se+row, se); atomicAdd(g_ss+row, sq); }
                if (hit && tg != -100) atomicAdd(g_tv+row, tval);
            }
        #pragma unroll
        for (int i = 0; i < 2; ++i)
            #pragma unroll
            for (int j = 0; j < 8; ++j)
                #pragma unroll
                for (int k = 0; k < 4; ++k) acc[i][j][k] = 0.f;

        // teacher phase: consume 0..61, issue teacher c+2
        for (int c = 0; c < T_CHN - 2; ++c) {
            WAIT_SYNC();
            issue_body(aT + (c + 2)*64, bT + (c + 2)*64, HT_, sIss); COMMIT(); ADV(sIss);
            mma_block(sCon); ADV(sCon);
        }
        // last two: commit-only
        for (int c = 0; c < 2; ++c) {
            WAIT_SYNC();
            COMMIT();
            mma_block(sCon); ADV(sCon);
        }

        // ---- epilogue 2: teacher stats + s.t
        #pragma unroll
        for (int im = 0; im < 2; ++im)
            #pragma unroll
            for (int h = 0; h < 2; ++h) {
                const int mloc = wm*32 + im*16 + (lane >> 2) + 8*h;
                const int row = row0 + mloc;
                float tt = 0.f, stv = 0.f;
                #pragma unroll
                for (int jt = 0; jt < 8; ++jt) {
                    float t0 = acc[im][jt][2*h], t1 = acc[im][jt][2*h+1];
                    const int nc = wn*64 + jt*8 + 2*(lane & 3);
                    uint32_t pr = g_stash[((size_t)row * V_ + (v0 + nc)) >> 1];
                    float2 sf = __bfloat1622float2(*(__nv_bfloat162*)&pr);
                    tt  += t0*t0 + t1*t1;
                    stv += sf.x*t0 + sf.y*t1;
                }
                tt  += __shfl_xor_sync(~0u, tt, 1);  tt  += __shfl_xor_sync(~0u, tt, 2);
                stv += __shfl_xor_sync(~0u, stv, 1); stv += __shfl_xor_sync(~0u, stv, 2);
                if ((lane & 3) == 0) { atomicAdd(g_tt+row, tt); atomicAdd(g_st+row, stv); }
            }
    }
}

__global__ void finalize_kernel(const long long* __restrict__ target, float* __restrict__ out) {
    __shared__ float red[256];
    const int tid = threadIdx.x;
    float acc = 0.f;
    for (int r = tid; r < BT_; r += 256) {
        float sn = fmaxf(sqrtf(g_ss[r]), 1e-12f);
        float tn = fmaxf(sqrtf(g_tt[r]), 1e-12f);
        float cosv = g_st[r] / (sn * tn);
        float nll = (target[r] != -100) ? (logf(g_se[r]) - g_tv[r]) : 0.f;
        acc += 0.5f * nll + 0.5f * (1.0f - cosv);
    }
    red[tid] = acc;
    __syncthreads();
    for (int s = 128; s > 0; s >>= 1) {
        if (tid < s) red[tid] += red[tid + s];
        __syncthreads();
    }
    if (tid == 0) out[0] = red[0] / (float)BT_;
}

extern "C" void kernel_launch(void* const* d_in, const int* in_sizes, int n_in,
                              void* d_out, int out_size) {
    const float* student = (const float*)d_in[0];
    const float* Ws      = (const float*)d_in[1];
    const float* teacher = (const float*)d_in[2];
    const float* Wt      = (const float*)d_in[3];
    const long long* tgt = (const long long*)d_in[4];
    float* out = (float*)d_out;

    cudaFuncSetAttribute(gemm_loss_kernel,
                         cudaFuncAttributeMaxDynamicSharedMemorySize, SMEM_BYTES);

    int total8 = M1 + M2 + M3 + M4;
    cvt_all_kernel<<<(total8 + 255) / 256, 256>>>((const float4*)student, (const float4*)Ws,
                                                  (const float4*)teacher, (const float4*)Wt);
    zeroA_kernel<<<4, 256>>>();
    zeroB_kernel<<<4, 256>>>();   // gemm stays 4th launch for ncu capture

    gemm_loss_kernel<<<NCTA, 256, SMEM_BYTES>>>(tgt);   // persistent: 2 CTAs/SM, dynamic tiles
    finalize_kernel<<<1, 256>>>(tgt, out);
}

// round 17
// speedup vs baseline: 1.2493x; 1.2493x over previous
#include <cuda_runtime.h>
#include <cuda_bf16.h>
#include <cstdint>

#define BT_ 2048
#define V_  32000
#define HS_ 2048
#define HT_ 4096
#define S_CH 32
#define N_CH 96
#define T_CHN (N_CH - S_CH)
#define STAGE_B 32768
#define SMEM_BYTES (3*STAGE_B)

__device__ float g_se[BT_], g_ss[BT_], g_tt[BT_], g_st[BT_], g_tv[BT_];
__device__ __align__(16) __nv_bfloat16 g_sb[(size_t)BT_*HS_];
__device__ __align__(16) __nv_bfloat16 g_wsb[(size_t)V_*HS_];
__device__ __align__(16) __nv_bfloat16 g_tb[(size_t)BT_*HT_];
__device__ __align__(16) __nv_bfloat16 g_wtb[(size_t)V_*HT_];
__device__ __align__(16) uint32_t g_stash[(size_t)BT_*V_/2];

#define M1 (BT_*HS_/8)
#define M2 (V_*HS_/8)
#define M3 (BT_*HT_/8)
#define M4 (V_*HT_/8)

__global__ void cvt_all_kernel(const float4* __restrict__ s0, const float4* __restrict__ s1,
                               const float4* __restrict__ s2, const float4* __restrict__ s3) {
    int i = blockIdx.x * blockDim.x + threadIdx.x;
    const float4* src; uint4* dst; int j;
    if (i < M1)                { src = s0; dst = (uint4*)g_sb;  j = i; }
    else if (i < M1+M2)        { src = s1; dst = (uint4*)g_wsb; j = i - M1; }
    else if (i < M1+M2+M3)     { src = s2; dst = (uint4*)g_tb;  j = i - (M1+M2); }
    else if (i < M1+M2+M3+M4)  { src = s3; dst = (uint4*)g_wtb; j = i - (M1+M2+M3); }
    else return;
    float4 a = src[2*j], b = src[2*j+1];
    __nv_bfloat162 p0 = __floats2bfloat162_rn(a.x, a.y);
    __nv_bfloat162 p1 = __floats2bfloat162_rn(a.z, a.w);
    __nv_bfloat162 p2 = __floats2bfloat162_rn(b.x, b.y);
    __nv_bfloat162 p3 = __floats2bfloat162_rn(b.z, b.w);
    uint4 o;
    o.x = *(uint32_t*)&p0; o.y = *(uint32_t*)&p1;
    o.z = *(uint32_t*)&p2; o.w = *(uint32_t*)&p3;
    dst[j] = o;
}
__global__ void zeroA_kernel() {
    int i = blockIdx.x * blockDim.x + threadIdx.x;
    if (i < 1024) { g_se[i]=0.f; g_ss[i]=0.f; g_tt[i]=0.f; g_st[i]=0.f; g_tv[i]=0.f; }
}
__global__ void zeroB_kernel() {
    int i = 1024 + blockIdx.x * blockDim.x + threadIdx.x;
    if (i < BT_) { g_se[i]=0.f; g_ss[i]=0.f; g_tt[i]=0.f; g_st[i]=0.f; g_tv[i]=0.f; }
}

__device__ __forceinline__ void cp16(uint32_t dst, const void* src) {
    asm volatile("cp.async.cg.shared.global [%0], [%1], 16;" :: "r"(dst), "l"(src) : "memory");
}
#define LDSM4(R0,R1,R2,R3,ADDR) \
    asm volatile("ldmatrix.sync.aligned.m8n8.x4.shared.b16 {%0,%1,%2,%3}, [%4];" \
        : "=r"(R0),"=r"(R1),"=r"(R2),"=r"(R3) : "r"(ADDR))
#define MMA(D,A0,A1,A2,A3,B0,B1) \
    asm volatile("mma.sync.aligned.m16n8k16.row.col.f32.bf16.bf16.f32 " \
        "{%0,%1,%2,%3},{%4,%5,%6,%7},{%8,%9},{%0,%1,%2,%3};" \
        : "+f"((D)[0]),"+f"((D)[1]),"+f"((D)[2]),"+f"((D)[3]) \
        : "r"(A0),"r"(A1),"r"(A2),"r"(A3),"r"(B0),"r"(B1))

#define ADV(s) s = ((s) == 2) ? 0 : (s) + 1
#define WAIT_SYNC() do { \
    asm volatile("cp.async.wait_group 1;" ::: "memory"); \
    __syncthreads(); } while (0)
#define COMMIT() asm volatile("cp.async.commit_group;" ::: "memory")

__global__ void __launch_bounds__(256, 2)
gemm_loss_kernel(const long long* __restrict__ target) {
    extern __shared__ char sm[];
    const uint32_t sm0 = (uint32_t)__cvta_generic_to_shared(sm);
    const int tid = threadIdx.x, lane = tid & 31, wid = tid >> 5;
    const int wm = wid & 3, wn = wid >> 2;            // 4x2 warps, warp tile 32x64
    const int r8 = lane & 7, sel = lane >> 3;
    const int row0 = blockIdx.x * 128, v0 = blockIdx.y * 128;

    const int rowA = wm*32 + r8 + 8*(sel & 1);
    const uint32_t baseA = (uint32_t)(rowA * 128);
    const uint32_t xorA  = (uint32_t)(rowA & 7);
    const uint32_t uA    = (uint32_t)(sel >> 1);
    const int rowB = wn*64 + r8 + 8*(sel >> 1);
    const uint32_t baseB = 16384u + (uint32_t)(rowB * 128);
    const uint32_t xorB  = (uint32_t)(rowB & 7);
    const uint32_t uB    = (uint32_t)(sel & 1);

    const int prow = tid >> 3;
    const int pu   = tid & 7;
    const uint32_t pswz = (uint32_t)((pu ^ (prow & 7)) << 4);

    const __nv_bfloat16* aS = g_sb  + (size_t)row0*HS_ + (size_t)prow*HS_ + pu*8;
    const __nv_bfloat16* bS = g_wsb + (size_t)v0 *HS_ + (size_t)prow*HS_ + pu*8;
    const __nv_bfloat16* aT = g_tb  + (size_t)row0*HT_ + (size_t)prow*HT_ + pu*8;
    const __nv_bfloat16* bT = g_wtb + (size_t)v0 *HT_ + (size_t)prow*HT_ + pu*8;

    float acc[2][8][4];
    #pragma unroll
    for (int i = 0; i < 2; ++i)
        #pragma unroll
        for (int j = 0; j < 8; ++j)
            #pragma unroll
            for (int k = 0; k < 4; ++k) acc[i][j][k] = 0.f;

    int sIss = 2, sCon = 0;

    auto issue_body = [&](const __nv_bfloat16* asrc, const __nv_bfloat16* bsrc, int K, int s) {
        const uint32_t st = sm0 + (uint32_t)s * STAGE_B;
        #pragma unroll
        for (int i = 0; i < 4; ++i)
            cp16(st + (prow + i*32)*128 + pswz, asrc + (size_t)(i*32)*K);
        #pragma unroll
        for (int i = 0; i < 4; ++i)
            cp16(st + 16384 + (prow + i*32)*128 + pswz, bsrc + (size_t)(i*32)*K);
    };

    auto mma_block = [&](int s) {
        const uint32_t st = sm0 + (uint32_t)s * STAGE_B;
        #pragma unroll
        for (int ks = 0; ks < 4; ++ks) {
            uint32_t A0,A1,A2,A3, A4,A5,A6,A7;
            const uint32_t ua = 2u*ks + uA;
            LDSM4(A0,A1,A2,A3, st + baseA + ((ua ^ xorA) << 4));
            LDSM4(A4,A5,A6,A7, st + baseA + 2048 + ((ua ^ xorA) << 4));
            const uint32_t ub = 2u*ks + uB;
            #pragma unroll
            for (int jj = 0; jj < 4; ++jj) {
                uint32_t B0,B1,B2,B3;
                LDSM4(B0,B1,B2,B3, st + baseB + jj*2048 + ((ub ^ xorB) << 4));
                MMA(acc[0][2*jj],   A0,A1,A2,A3, B0,B1);
                MMA(acc[0][2*jj+1], A0,A1,A2,A3, B2,B3);
                MMA(acc[1][2*jj],   A4,A5,A6,A7, B0,B1);
                MMA(acc[1][2*jj+1], A4,A5,A6,A7, B2,B3);
            }
        }
    };

    issue_body(aS,      bS,      HS_, 0); COMMIT();
    issue_body(aS + 64, bS + 64, HS_, 1); COMMIT();

    // student phase: consume 0..29, issue student c+2
    for (int c = 0; c < S_CH - 2; ++c) {
        WAIT_SYNC();
        issue_body(aS + (c + 2)*64, bS + (c + 2)*64, HS_, sIss); COMMIT(); ADV(sIss);
        mma_block(sCon); ADV(sCon);
    }
    // consume 30,31; issue teacher 0,1
    for (int c = 0; c < 2; ++c) {
        WAIT_SYNC();
        issue_body(aT + c*64, bT + c*64, HT_, sIss); COMMIT(); ADV(sIss);
        mma_block(sCon); ADV(sCon);
    }

    // ---- epilogue 1: student stats; stash s (bf16x2) to global
    #pragma unroll
    for (int im = 0; im < 2; ++im)
        #pragma unroll
        for (int h = 0; h < 2; ++h) {
            const int mloc = wm*32 + im*16 + (lane >> 2) + 8*h;
            const int row = row0 + mloc;
            const long long tg = target[row];
            const int tcol = (int)tg - v0;
            float se = 0.f, sq = 0.f, tval = 0.f; int hit = 0;
            #pragma unroll
            for (int jt = 0; jt < 8; ++jt) {
                float x0 = acc[im][jt][2*h], x1 = acc[im][jt][2*h+1];
                se += __expf(x0) + __expf(x1);
                sq += x0*x0 + x1*x1;
                const int nc = wn*64 + jt*8 + 2*(lane & 3);
                if (nc == tcol)     { tval = x0; hit = 1; }
                if (nc + 1 == tcol) { tval = x1; hit = 1; }
                __nv_bfloat162 p = __floats2bfloat162_rn(x0, x1);
                g_stash[((size_t)row * V_ + (v0 + nc)) >> 1] = *(uint32_t*)&p;
            }
            se += __shfl_xor_sync(~0u, se, 1); se += __shfl_xor_sync(~0u, se, 2);
            sq += __shfl_xor_sync(~0u, sq, 1); sq += __shfl_xor_sync(~0u, sq, 2);
            if ((lane & 3) == 0) { atomicAdd(g_se+row, se); atomicAdd(g_ss+row, sq); }
            if (hit && tg != -100) atomicAdd(g_tv+row, tval);
        }
    #pragma unroll
    for (int i = 0; i < 2; ++i)
        #pragma unroll
        for (int j = 0; j < 8; ++j)
            #pragma unroll
            for (int k = 0; k < 4; ++k) acc[i][j][k] = 0.f;

    // teacher phase: consume 0..61, issue teacher c+2
    for (int c = 0; c < T_CHN - 2; ++c) {
        WAIT_SYNC();
        issue_body(aT + (c + 2)*64, bT + (c + 2)*64, HT_, sIss); COMMIT(); ADV(sIss);
        mma_block(sCon); ADV(sCon);
    }
    // last two: commit-only
    for (int c = 0; c < 2; ++c) {
        WAIT_SYNC();
        COMMIT();
        mma_block(sCon); ADV(sCon);
    }

    // ---- epilogue 2: teacher stats + s.t
    #pragma unroll
    for (int im = 0; im < 2; ++im)
        #pragma unroll
        for (int h = 0; h < 2; ++h) {
            const int mloc = wm*32 + im*16 + (lane >> 2) + 8*h;
            const int row = row0 + mloc;
            float tt = 0.f, stv = 0.f;
            #pragma unroll
            for (int jt = 0; jt < 8; ++jt) {
                float t0 = acc[im][jt][2*h], t1 = acc[im][jt][2*h+1];
                const int nc = wn*64 + jt*8 + 2*(lane & 3);
                uint32_t pr = g_stash[((size_t)row * V_ + (v0 + nc)) >> 1];
                float2 sf = __bfloat1622float2(*(__nv_bfloat162*)&pr);
                tt  += t0*t0 + t1*t1;
                stv += sf.x*t0 + sf.y*t1;
            }
            tt  += __shfl_xor_sync(~0u, tt, 1);  tt  += __shfl_xor_sync(~0u, tt, 2);
            stv += __shfl_xor_sync(~0u, stv, 1); stv += __shfl_xor_sync(~0u, stv, 2);
            if ((lane & 3) == 0) { atomicAdd(g_tt+row, tt); atomicAdd(g_st+row, stv); }
        }
}

__global__ void finalize_kernel(const long long* __restrict__ target, float* __restrict__ out) {
    __shared__ float red[256];
    const int tid = threadIdx.x;
    float acc = 0.f;
    for (int r = tid; r < BT_; r += 256) {
        float sn = fmaxf(sqrtf(g_ss[r]), 1e-12f);
        float tn = fmaxf(sqrtf(g_tt[r]), 1e-12f);
        float cosv = g_st[r] / (sn * tn);
        float nll = (target[r] != -100) ? (logf(g_se[r]) - g_tv[r]) : 0.f;
        acc += 0.5f * nll + 0.5f * (1.0f - cosv);
    }
    red[tid] = acc;
    __syncthreads();
    for (int s = 128; s > 0; s >>= 1) {
        if (tid < s) red[tid] += red[tid + s];
        __syncthreads();
    }
    if (tid == 0) out[0] = red[0] / (float)BT_;
}

extern "C" void kernel_launch(void* const* d_in, const int* in_sizes, int n_in,
                              void* d_out, int out_size) {
    const float* student = (const float*)d_in[0];
    const float* Ws      = (const float*)d_in[1];
    const float* teacher = (const float*)d_in[2];
    const float* Wt      = (const float*)d_in[3];
    const long long* tgt = (const long long*)d_in[4];
    float* out = (float*)d_out;

    cudaFuncSetAttribute(gemm_loss_kernel,
                         cudaFuncAttributeMaxDynamicSharedMemorySize, SMEM_BYTES);

    int total8 = M1 + M2 + M3 + M4;
    cvt_all_kernel<<<(total8 + 255) / 256, 256>>>((const float4*)student, (const float4*)Ws,
                                                  (const float4*)teacher, (const float4*)Wt);
    zeroA_kernel<<<4, 256>>>();
    zeroB_kernel<<<4, 256>>>();

    dim3 grid(BT_/128, V_/128);   // (16, 250) static grid: wave-synchronized B-strip reuse in L2
    gemm_loss_kernel<<<grid, 256, SMEM_BYTES>>>(tgt);
    finalize_kernel<<<1, 256>>>(tgt, out);
}